// round 1
// baseline (speedup 1.0000x reference)
#include <cuda_runtime.h>
#include <cstdint>
#include <cstddef>

// ---------------- problem constants ----------------
constexpr int T_TASKS = 4;
constexpr int NE_S    = 4;     // specific experts per task
constexpr int NE_SH   = 4;     // shared experts
constexpr int DD      = 1024;  // model dim
constexpr int HH      = 2048;  // hidden dim
constexpr int BB      = 4096;  // batch
constexpr int N_EXP   = 20;    // 4 shared + 16 specific

// ---------------- scratch (static device globals; no allocation) ----------------
__device__ float g_hidden[(size_t)N_EXP * BB * HH];   // 671 MB
__device__ float g_expout[(size_t)N_EXP * BB * DD];   // 335 MB
__device__ float g_gw[(size_t)T_TASKS * BB * 8];      // per-task gates
__device__ float g_sgw[(size_t)BB * 20];              // shared gate

// ---------------- f32x2 packed-FMA helpers (FFMA2: ptxas won't auto-emit) ----------------
__device__ __forceinline__ unsigned long long pack2dup(float x) {
    unsigned long long r;
    asm("mov.b64 %0, {%1, %1};" : "=l"(r) : "f"(x));
    return r;
}
__device__ __forceinline__ void ffma2(unsigned long long& c, unsigned long long a, unsigned long long b) {
    asm("fma.rn.f32x2 %0, %1, %2, %0;" : "+l"(c) : "l"(a), "l"(b));
}
__device__ __forceinline__ float2 unpack2(unsigned long long c) {
    float2 f;
    asm("mov.b64 {%0, %1}, %2;" : "=f"(f.x), "=f"(f.y) : "l"(c));
    return f;
}

// ---------------- tiled SGEMM: C[4096,N] = A[4096,K] @ B[K,N] + bias, optional relu ----------
constexpr int BM = 128, BN = 128, BK = 16;

template <bool RELU, int K, int N>
__device__ __forceinline__ void gemm_tile(const float* __restrict__ A,
                                          const float* __restrict__ Bw,
                                          const float* __restrict__ bias,
                                          float* __restrict__ Out)
{
    __shared__ float As[2][BK][BM + 4];   // transposed A tile, padded vs bank conflicts
    __shared__ float Bs[2][BK][BN];

    const int tid = threadIdx.x;

    // global-load lanes
    const int a_r = tid >> 2;             // 0..63 (two rows: a_r, a_r+64)
    const int a_c = (tid & 3) << 2;       // 0,4,8,12
    const int b_r = tid >> 5;             // 0..7  (two rows: b_r, b_r+8)
    const int b_c = (tid & 31) << 2;      // 0..124

    const float* Ag = A + (size_t)(blockIdx.y * BM + a_r) * K + a_c;
    const float* Bg = Bw + (size_t)b_r * N + blockIdx.x * BN + b_c;

    // compute lanes: 8x8 micro tile
    const int tm = (tid >> 4) << 3;
    const int tn = (tid & 15) << 3;

    float4 ar0, ar1, br0, br1;

    // prologue: tile 0 -> buf 0
    ar0 = *(const float4*)(Ag);
    ar1 = *(const float4*)(Ag + (size_t)64 * K);
    br0 = *(const float4*)(Bg);
    br1 = *(const float4*)(Bg + (size_t)8 * N);

    As[0][a_c + 0][a_r]      = ar0.x; As[0][a_c + 1][a_r]      = ar0.y;
    As[0][a_c + 2][a_r]      = ar0.z; As[0][a_c + 3][a_r]      = ar0.w;
    As[0][a_c + 0][a_r + 64] = ar1.x; As[0][a_c + 1][a_r + 64] = ar1.y;
    As[0][a_c + 2][a_r + 64] = ar1.z; As[0][a_c + 3][a_r + 64] = ar1.w;
    *(float4*)&Bs[0][b_r][b_c]     = br0;
    *(float4*)&Bs[0][b_r + 8][b_c] = br1;
    __syncthreads();

    unsigned long long acc[8][4];
#pragma unroll
    for (int i = 0; i < 8; i++)
#pragma unroll
        for (int j = 0; j < 4; j++) acc[i][j] = 0ULL;

    constexpr int NK = K / BK;
    for (int kt = 0; kt < NK; kt++) {
        const int buf = kt & 1;
        if (kt + 1 < NK) {
            const float* Agn = Ag + (size_t)(kt + 1) * BK;
            ar0 = *(const float4*)(Agn);
            ar1 = *(const float4*)(Agn + (size_t)64 * K);
            const float* Bgn = Bg + (size_t)(kt + 1) * BK * N;
            br0 = *(const float4*)(Bgn);
            br1 = *(const float4*)(Bgn + (size_t)8 * N);
        }
#pragma unroll
        for (int kk = 0; kk < BK; kk++) {
            float4 a0 = *(const float4*)&As[buf][kk][tm];
            float4 a1 = *(const float4*)&As[buf][kk][tm + 4];
            ulonglong2 bq0 = *(const ulonglong2*)&Bs[buf][kk][tn];
            ulonglong2 bq1 = *(const ulonglong2*)&Bs[buf][kk][tn + 4];
            const unsigned long long bp0 = bq0.x, bp1 = bq0.y, bp2 = bq1.x, bp3 = bq1.y;
            const float av[8] = {a0.x, a0.y, a0.z, a0.w, a1.x, a1.y, a1.z, a1.w};
#pragma unroll
            for (int i = 0; i < 8; i++) {
                const unsigned long long ad = pack2dup(av[i]);
                ffma2(acc[i][0], ad, bp0);
                ffma2(acc[i][1], ad, bp1);
                ffma2(acc[i][2], ad, bp2);
                ffma2(acc[i][3], ad, bp3);
            }
        }
        if (kt + 1 < NK) {
            const int nb = buf ^ 1;
            As[nb][a_c + 0][a_r]      = ar0.x; As[nb][a_c + 1][a_r]      = ar0.y;
            As[nb][a_c + 2][a_r]      = ar0.z; As[nb][a_c + 3][a_r]      = ar0.w;
            As[nb][a_c + 0][a_r + 64] = ar1.x; As[nb][a_c + 1][a_r + 64] = ar1.y;
            As[nb][a_c + 2][a_r + 64] = ar1.z; As[nb][a_c + 3][a_r + 64] = ar1.w;
            *(float4*)&Bs[nb][b_r][b_c]     = br0;
            *(float4*)&Bs[nb][b_r + 8][b_c] = br1;
        }
        __syncthreads();
    }

    // epilogue: + bias, optional relu, store
    float bv[8];
    const float* bb = bias + blockIdx.x * BN + tn;
#pragma unroll
    for (int j = 0; j < 8; j++) bv[j] = bb[j];

    float* Orow = Out + (size_t)(blockIdx.y * BM + tm) * N + blockIdx.x * BN + tn;
#pragma unroll
    for (int i = 0; i < 8; i++) {
        float r[8];
#pragma unroll
        for (int j = 0; j < 4; j++) {
            float2 f = unpack2(acc[i][j]);
            r[2 * j]     = f.x + bv[2 * j];
            r[2 * j + 1] = f.y + bv[2 * j + 1];
            if (RELU) {
                r[2 * j]     = fmaxf(r[2 * j], 0.f);
                r[2 * j + 1] = fmaxf(r[2 * j + 1], 0.f);
            }
        }
        *(float4*)(Orow + (size_t)i * N)     = make_float4(r[0], r[1], r[2], r[3]);
        *(float4*)(Orow + (size_t)i * N + 4) = make_float4(r[4], r[5], r[6], r[7]);
    }
}

// ---------------- expert layer kernels (blockIdx.z = expert 0..19) ----------------
__global__ __launch_bounds__(256, 2)
void expert_l1(const float* __restrict__ task_reps, const float* __restrict__ shared_rep,
               const float* __restrict__ spec_w1, const float* __restrict__ spec_b1,
               const float* __restrict__ shr_w1, const float* __restrict__ shr_b1)
{
    const int z = blockIdx.z;
    const float *A, *W, *bias;
    if (z < NE_SH) {
        A    = shared_rep;
        W    = shr_w1 + (size_t)z * DD * HH;
        bias = shr_b1 + (size_t)z * HH;
    } else {
        const int te = z - NE_SH;             // t*4 + e
        A    = task_reps + (size_t)(te >> 2) * BB * DD;
        W    = spec_w1 + (size_t)te * DD * HH;
        bias = spec_b1 + (size_t)te * HH;
    }
    float* out = g_hidden + (size_t)z * BB * HH;
    gemm_tile<true, DD, HH>(A, W, bias, out);
}

__global__ __launch_bounds__(256, 2)
void expert_l2(const float* __restrict__ spec_w2, const float* __restrict__ spec_b2,
               const float* __restrict__ shr_w2, const float* __restrict__ shr_b2)
{
    const int z = blockIdx.z;
    const float* A = g_hidden + (size_t)z * BB * HH;
    const float *W, *bias;
    if (z < NE_SH) {
        W    = shr_w2 + (size_t)z * HH * DD;
        bias = shr_b2 + (size_t)z * DD;
    } else {
        const int te = z - NE_SH;
        W    = spec_w2 + (size_t)te * HH * DD;
        bias = spec_b2 + (size_t)te * DD;
    }
    float* out = g_expout + (size_t)z * BB * DD;
    gemm_tile<false, HH, DD>(A, W, bias, out);
}

// ---------------- gate kernels ----------------
// per-task gates: one warp per (t,b) row; logits over 8 experts, softmax.
__global__ __launch_bounds__(256)
void gates_task(const float* __restrict__ task_reps,
                const float* __restrict__ gate_w, const float* __restrict__ gate_b)
{
    const int warp = blockIdx.x * 8 + (threadIdx.x >> 5);
    const int lane = threadIdx.x & 31;
    const int t = warp / BB;
    const int b = warp % BB;
    const float* x = task_reps + (size_t)warp * DD;            // (t*BB + b) row
    const float* W = gate_w + (size_t)t * DD * 8;

    const int e = lane & 7, part = lane >> 3;
    float s = 0.f;
#pragma unroll 4
    for (int i = 0; i < DD / 4; i++) {
        const int d = part + 4 * i;
        s += x[d] * W[32 * i + lane];                          // W[d*8 + e] == W[32i + lane]
    }
    s += __shfl_xor_sync(0xffffffffu, s, 8);
    s += __shfl_xor_sync(0xffffffffu, s, 16);
    s += gate_b[t * 8 + e];

    float m = s;
    m = fmaxf(m, __shfl_xor_sync(0xffffffffu, m, 1));
    m = fmaxf(m, __shfl_xor_sync(0xffffffffu, m, 2));
    m = fmaxf(m, __shfl_xor_sync(0xffffffffu, m, 4));
    float ex = expf(s - m);
    float sum = ex;
    sum += __shfl_xor_sync(0xffffffffu, sum, 1);
    sum += __shfl_xor_sync(0xffffffffu, sum, 2);
    sum += __shfl_xor_sync(0xffffffffu, sum, 4);
    if (lane < 8) g_gw[(size_t)warp * 8 + lane] = ex / sum;
}

// shared gate: one warp per b row; logits over 20 experts, softmax.
__global__ __launch_bounds__(256)
void gates_shared(const float* __restrict__ shared_rep,
                  const float* __restrict__ sgate_w, const float* __restrict__ sgate_b)
{
    const int b = blockIdx.x * 8 + (threadIdx.x >> 5);
    const int lane = threadIdx.x & 31;
    const float* x = shared_rep + (size_t)b * DD;

    float s = 0.f;
    if (lane < 20) {
#pragma unroll 4
        for (int d = 0; d < DD; d++) s += x[d] * sgate_w[d * 20 + lane];
        s += sgate_b[lane];
    }
    float v = (lane < 20) ? s : -3.402823466e38f;
    float m = v;
    m = fmaxf(m, __shfl_xor_sync(0xffffffffu, m, 16));
    m = fmaxf(m, __shfl_xor_sync(0xffffffffu, m, 8));
    m = fmaxf(m, __shfl_xor_sync(0xffffffffu, m, 4));
    m = fmaxf(m, __shfl_xor_sync(0xffffffffu, m, 2));
    m = fmaxf(m, __shfl_xor_sync(0xffffffffu, m, 1));
    float ex = (lane < 20) ? expf(s - m) : 0.f;
    float sum = ex;
    sum += __shfl_xor_sync(0xffffffffu, sum, 16);
    sum += __shfl_xor_sync(0xffffffffu, sum, 8);
    sum += __shfl_xor_sync(0xffffffffu, sum, 4);
    sum += __shfl_xor_sync(0xffffffffu, sum, 2);
    sum += __shfl_xor_sync(0xffffffffu, sum, 1);
    if (lane < 20) g_sgw[(size_t)b * 20 + lane] = ex / sum;
}

// ---------------- combine: gated mixture -> 5 output tensors ----------------
__global__ __launch_bounds__(256)
void combine(float* __restrict__ out)
{
    __shared__ float gw_s[T_TASKS][8];
    __shared__ float sgw_s[20];
    const int b = blockIdx.y;
    const int d = blockIdx.x * 256 + threadIdx.x;
    const int tid = threadIdx.x;

    if (tid < 32) {
        gw_s[tid >> 3][tid & 7] = g_gw[((size_t)(tid >> 3) * BB + b) * 8 + (tid & 7)];
    } else if (tid < 52) {
        sgw_s[tid - 32] = g_sgw[(size_t)b * 20 + (tid - 32)];
    }
    __syncthreads();

    float at[T_TASKS] = {0.f, 0.f, 0.f, 0.f};
    float ash = 0.f;
#pragma unroll
    for (int z = 0; z < N_EXP; z++) {
        const float v = g_expout[((size_t)z * BB + b) * DD + d];
        ash += sgw_s[z] * v;
        if (z < NE_SH) {
#pragma unroll
            for (int t = 0; t < T_TASKS; t++) at[t] += gw_s[t][z] * v;
        } else {
            const int te = z - NE_SH;
            at[te >> 2] += gw_s[te >> 2][4 + (te & 3)] * v;
        }
    }
#pragma unroll
    for (int t = 0; t < T_TASKS; t++)
        out[((size_t)t * BB + b) * DD + d] = at[t];
    out[((size_t)T_TASKS * BB + b) * DD + d] = ash;
}

// ---------------- launch ----------------
extern "C" void kernel_launch(void* const* d_in, const int* in_sizes, int n_in,
                              void* d_out, int out_size)
{
    const float* task_reps  = (const float*)d_in[0];
    const float* shared_rep = (const float*)d_in[1];
    const float* spec_w1    = (const float*)d_in[2];
    const float* spec_b1    = (const float*)d_in[3];
    const float* spec_w2    = (const float*)d_in[4];
    const float* spec_b2    = (const float*)d_in[5];
    const float* shr_w1     = (const float*)d_in[6];
    const float* shr_b1     = (const float*)d_in[7];
    const float* shr_w2     = (const float*)d_in[8];
    const float* shr_b2     = (const float*)d_in[9];
    const float* gate_w     = (const float*)d_in[10];
    const float* gate_b     = (const float*)d_in[11];
    const float* sgate_w    = (const float*)d_in[12];
    const float* sgate_b    = (const float*)d_in[13];
    float* out = (float*)d_out;

    gates_task<<<T_TASKS * BB / 8, 256>>>(task_reps, gate_w, gate_b);
    gates_shared<<<BB / 8, 256>>>(shared_rep, sgate_w, sgate_b);
    expert_l1<<<dim3(HH / BN, BB / BM, N_EXP), 256>>>(task_reps, shared_rep,
                                                      spec_w1, spec_b1, shr_w1, shr_b1);
    expert_l2<<<dim3(DD / BN, BB / BM, N_EXP), 256>>>(spec_w2, spec_b2, shr_w2, shr_b2);
    combine<<<dim3(DD / 256, BB), 256>>>(out);
}

// round 3
// speedup vs baseline: 2.2899x; 2.2899x over previous
#include <cuda_runtime.h>
#include <cuda_bf16.h>
#include <cstdint>
#include <cstddef>

// ---------------- problem constants ----------------
constexpr int T_TASKS = 4;
constexpr int NE_SH   = 4;
constexpr int DD      = 1024;
constexpr int HH      = 2048;
constexpr int BB      = 4096;
constexpr int N_EXP   = 20;

// ---------------- scratch ----------------
__device__ float g_hidden[(size_t)N_EXP * BB * HH];
__device__ float g_expout[(size_t)N_EXP * BB * DD];
__device__ float g_gw[(size_t)T_TASKS * BB * 8];
__device__ float g_sgw[(size_t)BB * 20];

// ---------------- GEMM config ----------------
constexpr int BM = 256, BN = 128, BK = 32;
constexpr int ROWW32 = 20;                    // uint32 words per smem row (16 data pairs + 4 pad)
constexpr int A_T32  = BM * ROWW32;           // 5120 words
constexpr int B_T32  = BN * ROWW32;           // 2560 words
constexpr int STG32  = 2 * A_T32 + 2 * B_T32; // 15360 words per stage
constexpr size_t SMEM_BYTES = 2ull * STG32 * 4ull;  // 122880 B

// ---------------- helpers ----------------
// split two fp32 into bf16 hi pair + exact residual bf16 lo pair.
// packed word: low half = first elem (even k), high half = second (odd k).
__device__ __forceinline__ void split2(float x0, float x1, uint32_t& h, uint32_t& l) {
    __nv_bfloat162 hb = __floats2bfloat162_rn(x0, x1);
    h = *reinterpret_cast<uint32_t*>(&hb);
    float h0 = __bfloat162float(hb.x);
    float h1 = __bfloat162float(hb.y);
    __nv_bfloat162 lb = __floats2bfloat162_rn(x0 - h0, x1 - h1);
    l = *reinterpret_cast<uint32_t*>(&lb);
}

__device__ __forceinline__ void mma_bf16(float* d, const uint32_t* a, uint32_t b0, uint32_t b1) {
    asm volatile(
        "mma.sync.aligned.m16n8k16.row.col.f32.bf16.bf16.f32 "
        "{%0,%1,%2,%3}, {%4,%5,%6,%7}, {%8,%9}, {%0,%1,%2,%3};"
        : "+f"(d[0]), "+f"(d[1]), "+f"(d[2]), "+f"(d[3])
        : "r"(a[0]), "r"(a[1]), "r"(a[2]), "r"(a[3]), "r"(b0), "r"(b1));
}

// ---------------- bf16x3 tensor-core GEMM ----------------
// Out[m, n] = A[m, :] @ W[:, n] + bias[n]   (A: [B,K] row-major, W: [K,N] row-major)
template <int K, int NOUT, bool RELU, bool IS_L1>
__global__ void __launch_bounds__(256, 1)
mma_gemm(const float* __restrict__ task_reps, const float* __restrict__ shared_rep,
         const float* __restrict__ bias_shr, const float* __restrict__ bias_spec)
{
    extern __shared__ __align__(16) uint32_t sm32[];
    const int tid = threadIdx.x, lane = tid & 31, wid = tid >> 5;
    const int wm = wid & 3, wn = wid >> 2;         // 4 x 2 warp grid
    const int gID = lane >> 2, tg = lane & 3;
    const int z  = blockIdx.z;
    const int m0 = blockIdx.y * BM, n0 = blockIdx.x * BN;

    const float *A, *W, *bias;
    float* Out;
    if (IS_L1) {
        A    = (z < NE_SH) ? shared_rep
                           : task_reps + (size_t)((z - NE_SH) >> 2) * BB * K;
        W    = ((z < NE_SH) ? (const float*)nullptr : nullptr), W = nullptr;  // set below
    }
    // weight/bias/output selection (bias_shr points at shr weights' bias array etc.)
    const float* Wshr;
    const float* Wspec;
    if (IS_L1) {
        Wshr  = bias_shr  - 0;  // placeholder, real pointers passed via globals below
    }
    // NOTE: to keep the template simple we pass weights through extra params:
    // (see kernel_launch — we re-purpose: bias_shr = shr_w, bias_spec = spec_w is NOT done;
    //  instead weights are passed via __grid_constant__-free plain params below)
    // -- this block intentionally replaced by the real parameterization:
    (void)Wshr; (void)Wspec; (void)W; (void)A; (void)bias; (void)Out;
    asm volatile("trap;");  // never compiled-in: see mma_gemm2
}

// Clean parameterization: explicit weight pointers.
template <int K, int NOUT, bool RELU>
__global__ void __launch_bounds__(256, 1)
mma_gemm2(const float* __restrict__ Abase_shared, const float* __restrict__ Abase_task,
          const float* __restrict__ w_shr, const float* __restrict__ w_spec,
          const float* __restrict__ b_shr, const float* __restrict__ b_spec,
          float* __restrict__ OutBase, int a_is_split)
{
    extern __shared__ __align__(16) uint32_t sm32[];
    const int tid = threadIdx.x, lane = tid & 31, wid = tid >> 5;
    const int wm = wid & 3, wn = wid >> 2;
    const int gID = lane >> 2, tg = lane & 3;
    const int z  = blockIdx.z;
    const int m0 = blockIdx.y * BM, n0 = blockIdx.x * BN;

    const float* A;
    if (a_is_split) {   // L1: shared experts read shared_rep, specific read task_reps
        A = (z < NE_SH) ? Abase_shared
                        : Abase_task + (size_t)((z - NE_SH) >> 2) * BB * K;
    } else {            // L2: A = hidden activations of expert z
        A = Abase_shared + (size_t)z * BB * K;
    }
    const float* W    = (z < NE_SH) ? w_shr + (size_t)z * K * NOUT
                                    : w_spec + (size_t)(z - NE_SH) * K * NOUT;
    const float* bias = (z < NE_SH) ? b_shr + (size_t)z * NOUT
                                    : b_spec + (size_t)(z - NE_SH) * NOUT;
    float* Out = OutBase + (size_t)z * BB * NOUT;

    const float* Ag = A + (size_t)m0 * K;

    float4 aSt[8];
    float  bSt[4][4];
    float  acc[4][8][4];
#pragma unroll
    for (int mt = 0; mt < 4; mt++)
#pragma unroll
        for (int nt = 0; nt < 8; nt++)
#pragma unroll
            for (int r = 0; r < 4; r++) acc[mt][nt][r] = 0.f;

    // --------- producer lambdas (manually inlined) ---------
    // A units: 256 rows x 8 float4 -> 8 iters; B units: 128 n x 8 kquads -> 4 iters.
#define LOAD_GLB(s)                                                                    \
    {                                                                                  \
        _Pragma("unroll")                                                              \
        for (int i = 0; i < 8; i++) {                                                  \
            const int unit = tid + 256 * i;                                            \
            const int m = unit >> 3, q = unit & 7;                                     \
            aSt[i] = *(const float4*)(Ag + (size_t)m * K + (s) * 32 + 4 * q);          \
        }                                                                              \
        _Pragma("unroll")                                                              \
        for (int i = 0; i < 4; i++) {                                                  \
            const int unit = tid + 256 * i;                                            \
            const int n = unit & 127, kq = unit >> 7;                                  \
            _Pragma("unroll")                                                          \
            for (int j = 0; j < 4; j++)                                                \
                bSt[i][j] = W[(size_t)((s) * 32 + 4 * kq + j) * NOUT + n0 + n];        \
        }                                                                              \
    }

#define STORE_SMEM(buf)                                                                \
    {                                                                                  \
        uint32_t* ahi = sm32 + (buf) * STG32;                                          \
        uint32_t* alo = ahi + A_T32;                                                   \
        uint32_t* bhi = ahi + 2 * A_T32;                                               \
        uint32_t* blo = bhi + B_T32;                                                   \
        _Pragma("unroll")                                                              \
        for (int i = 0; i < 8; i++) {                                                  \
            const int unit = tid + 256 * i;                                            \
            const int m = unit >> 3, q = unit & 7;                                     \
            uint32_t h0, l0, h1, l1;                                                   \
            split2(aSt[i].x, aSt[i].y, h0, l0);                                        \
            split2(aSt[i].z, aSt[i].w, h1, l1);                                        \
            const int wadr = m * ROWW32 + q * 2;                                       \
            *(uint2*)(ahi + wadr) = make_uint2(h0, h1);                                \
            *(uint2*)(alo + wadr) = make_uint2(l0, l1);                                \
        }                                                                              \
        _Pragma("unroll")                                                              \
        for (int i = 0; i < 4; i++) {                                                  \
            const int unit = tid + 256 * i;                                            \
            const int n = unit & 127, kq = unit >> 7;                                  \
            uint32_t h0, l0, h1, l1;                                                   \
            split2(bSt[i][0], bSt[i][1], h0, l0);                                      \
            split2(bSt[i][2], bSt[i][3], h1, l1);                                      \
            const int s4 = ((n >> 3) & 3) << 2;          /* XOR swizzle, bits 2-3 */   \
            const int wadr = n * ROWW32 + ((2 * kq) ^ s4);                             \
            *(uint2*)(bhi + wadr) = make_uint2(h0, h1);                                \
            *(uint2*)(blo + wadr) = make_uint2(l0, l1);                                \
        }                                                                              \
    }

    LOAD_GLB(0);
    STORE_SMEM(0);
    __syncthreads();

    constexpr int NS = K / BK;
    for (int s = 0; s < NS; s++) {
        const int buf = s & 1;
        if (s + 1 < NS) LOAD_GLB(s + 1);

        const uint32_t* ahi = sm32 + buf * STG32;
        const uint32_t* alo = ahi + A_T32;
        const uint32_t* bhi = ahi + 2 * A_T32;
        const uint32_t* blo = bhi + B_T32;

#pragma unroll
        for (int g = 0; g < 2; g++) {
            uint32_t ah[4][4], al[4][4];
#pragma unroll
            for (int mt = 0; mt < 4; mt++) {
                const int r = wm * 64 + mt * 16 + gID;
                const int b0 = r * ROWW32 + tg + 8 * g;
                ah[mt][0] = ahi[b0];
                ah[mt][1] = ahi[b0 + 8 * ROWW32];
                ah[mt][2] = ahi[b0 + 4];
                ah[mt][3] = ahi[b0 + 8 * ROWW32 + 4];
                al[mt][0] = alo[b0];
                al[mt][1] = alo[b0 + 8 * ROWW32];
                al[mt][2] = alo[b0 + 4];
                al[mt][3] = alo[b0 + 8 * ROWW32 + 4];
            }
#pragma unroll
            for (int nt = 0; nt < 8; nt++) {
                const int n  = wn * 64 + nt * 8 + gID;
                const int s4 = ((n >> 3) & 3) << 2;
                const int p0 = (tg + 8 * g) ^ s4;           // b0 word
                const int p1 = (tg + 4 + 8 * g) ^ s4;       // b1 word (k+8)
                const uint32_t bh0 = bhi[n * ROWW32 + p0];
                const uint32_t bh1 = bhi[n * ROWW32 + p1];
                const uint32_t bl0 = blo[n * ROWW32 + p0];
                const uint32_t bl1 = blo[n * ROWW32 + p1];
#pragma unroll
                for (int mt = 0; mt < 4; mt++) {
                    mma_bf16(acc[mt][nt], ah[mt], bh0, bh1);   // Ah*Bh
                    mma_bf16(acc[mt][nt], ah[mt], bl0, bl1);   // Ah*Bl
                    mma_bf16(acc[mt][nt], al[mt], bh0, bh1);   // Al*Bh
                }
            }
        }

        if (s + 1 < NS) STORE_SMEM(buf ^ 1);
        __syncthreads();
    }
#undef LOAD_GLB
#undef STORE_SMEM

    // --------- epilogue: bias (+relu), write fp32 ---------
#pragma unroll
    for (int nt = 0; nt < 8; nt++) {
        const int col = n0 + wn * 64 + nt * 8 + 2 * tg;
        const float2 bv = *(const float2*)(bias + col);
#pragma unroll
        for (int mt = 0; mt < 4; mt++) {
            const int row = m0 + wm * 64 + mt * 16 + gID;
            float v0 = acc[mt][nt][0] + bv.x;
            float v1 = acc[mt][nt][1] + bv.y;
            float v2 = acc[mt][nt][2] + bv.x;
            float v3 = acc[mt][nt][3] + bv.y;
            if (RELU) {
                v0 = fmaxf(v0, 0.f); v1 = fmaxf(v1, 0.f);
                v2 = fmaxf(v2, 0.f); v3 = fmaxf(v3, 0.f);
            }
            *(float2*)(Out + (size_t)row * NOUT + col)       = make_float2(v0, v1);
            *(float2*)(Out + (size_t)(row + 8) * NOUT + col) = make_float2(v2, v3);
        }
    }
}

// ---------------- gates (unchanged, validated R0) ----------------
__global__ __launch_bounds__(256)
void gates_task(const float* __restrict__ task_reps,
                const float* __restrict__ gate_w, const float* __restrict__ gate_b)
{
    const int warp = blockIdx.x * 8 + (threadIdx.x >> 5);
    const int lane = threadIdx.x & 31;
    const int t = warp / BB;
    const float* x = task_reps + (size_t)warp * DD;
    const float* W = gate_w + (size_t)t * DD * 8;

    const int e = lane & 7, part = lane >> 3;
    float s = 0.f;
#pragma unroll 4
    for (int i = 0; i < DD / 4; i++) {
        const int d = part + 4 * i;
        s += x[d] * W[32 * i + lane];
    }
    s += __shfl_xor_sync(0xffffffffu, s, 8);
    s += __shfl_xor_sync(0xffffffffu, s, 16);
    s += gate_b[t * 8 + e];

    float m = s;
    m = fmaxf(m, __shfl_xor_sync(0xffffffffu, m, 1));
    m = fmaxf(m, __shfl_xor_sync(0xffffffffu, m, 2));
    m = fmaxf(m, __shfl_xor_sync(0xffffffffu, m, 4));
    float ex = expf(s - m);
    float sum = ex;
    sum += __shfl_xor_sync(0xffffffffu, sum, 1);
    sum += __shfl_xor_sync(0xffffffffu, sum, 2);
    sum += __shfl_xor_sync(0xffffffffu, sum, 4);
    if (lane < 8) g_gw[(size_t)warp * 8 + lane] = ex / sum;
}

__global__ __launch_bounds__(256)
void gates_shared(const float* __restrict__ shared_rep,
                  const float* __restrict__ sgate_w, const float* __restrict__ sgate_b)
{
    const int b = blockIdx.x * 8 + (threadIdx.x >> 5);
    const int lane = threadIdx.x & 31;
    const float* x = shared_rep + (size_t)b * DD;

    float s = 0.f;
    if (lane < 20) {
#pragma unroll 4
        for (int d = 0; d < DD; d++) s += x[d] * sgate_w[d * 20 + lane];
        s += sgate_b[lane];
    }
    float v = (lane < 20) ? s : -3.402823466e38f;
    float m = v;
    m = fmaxf(m, __shfl_xor_sync(0xffffffffu, m, 16));
    m = fmaxf(m, __shfl_xor_sync(0xffffffffu, m, 8));
    m = fmaxf(m, __shfl_xor_sync(0xffffffffu, m, 4));
    m = fmaxf(m, __shfl_xor_sync(0xffffffffu, m, 2));
    m = fmaxf(m, __shfl_xor_sync(0xffffffffu, m, 1));
    float ex = (lane < 20) ? expf(s - m) : 0.f;
    float sum = ex;
    sum += __shfl_xor_sync(0xffffffffu, sum, 16);
    sum += __shfl_xor_sync(0xffffffffu, sum, 8);
    sum += __shfl_xor_sync(0xffffffffu, sum, 4);
    sum += __shfl_xor_sync(0xffffffffu, sum, 2);
    sum += __shfl_xor_sync(0xffffffffu, sum, 1);
    if (lane < 20) g_sgw[(size_t)b * 20 + lane] = ex / sum;
}

// ---------------- combine (unchanged, validated R0) ----------------
__global__ __launch_bounds__(256)
void combine(float* __restrict__ out)
{
    __shared__ float gw_s[T_TASKS][8];
    __shared__ float sgw_s[20];
    const int b = blockIdx.y;
    const int d = blockIdx.x * 256 + threadIdx.x;
    const int tid = threadIdx.x;

    if (tid < 32) {
        gw_s[tid >> 3][tid & 7] = g_gw[((size_t)(tid >> 3) * BB + b) * 8 + (tid & 7)];
    } else if (tid < 52) {
        sgw_s[tid - 32] = g_sgw[(size_t)b * 20 + (tid - 32)];
    }
    __syncthreads();

    float at[T_TASKS] = {0.f, 0.f, 0.f, 0.f};
    float ash = 0.f;
#pragma unroll
    for (int z = 0; z < N_EXP; z++) {
        const float v = g_expout[((size_t)z * BB + b) * DD + d];
        ash += sgw_s[z] * v;
        if (z < NE_SH) {
#pragma unroll
            for (int t = 0; t < T_TASKS; t++) at[t] += gw_s[t][z] * v;
        } else {
            const int te = z - NE_SH;
            at[te >> 2] += gw_s[te >> 2][4 + (te & 3)] * v;
        }
    }
#pragma unroll
    for (int t = 0; t < T_TASKS; t++)
        out[((size_t)t * BB + b) * DD + d] = at[t];
    out[((size_t)T_TASKS * BB + b) * DD + d] = ash;
}

// ---------------- launch ----------------
extern "C" void kernel_launch(void* const* d_in, const int* in_sizes, int n_in,
                              void* d_out, int out_size)
{
    const float* task_reps  = (const float*)d_in[0];
    const float* shared_rep = (const float*)d_in[1];
    const float* spec_w1    = (const float*)d_in[2];
    const float* spec_b1    = (const float*)d_in[3];
    const float* spec_w2    = (const float*)d_in[4];
    const float* spec_b2    = (const float*)d_in[5];
    const float* shr_w1     = (const float*)d_in[6];
    const float* shr_b1     = (const float*)d_in[7];
    const float* shr_w2     = (const float*)d_in[8];
    const float* shr_b2     = (const float*)d_in[9];
    const float* gate_w     = (const float*)d_in[10];
    const float* gate_b     = (const float*)d_in[11];
    const float* sgate_w    = (const float*)d_in[12];
    const float* sgate_b    = (const float*)d_in[13];
    float* out = (float*)d_out;

    float* g_hidden_p;  cudaGetSymbolAddress((void**)&g_hidden_p, g_hidden);
    float* g_expout_p;  cudaGetSymbolAddress((void**)&g_expout_p, g_expout);

    cudaFuncSetAttribute(mma_gemm2<DD, HH, true>,
                         cudaFuncAttributeMaxDynamicSharedMemorySize, (int)SMEM_BYTES);
    cudaFuncSetAttribute(mma_gemm2<HH, DD, false>,
                         cudaFuncAttributeMaxDynamicSharedMemorySize, (int)SMEM_BYTES);

    gates_task<<<T_TASKS * BB / 8, 256>>>(task_reps, gate_w, gate_b);
    gates_shared<<<BB / 8, 256>>>(shared_rep, sgate_w, sgate_b);

    // L1: [B,1024] @ [1024,2048] + b, relu  -> g_hidden
    mma_gemm2<DD, HH, true><<<dim3(HH / BN, BB / BM, N_EXP), 256, SMEM_BYTES>>>(
        shared_rep, task_reps, shr_w1, spec_w1, shr_b1, spec_b1, g_hidden_p, 1);
    // L2: [B,2048] @ [2048,1024] + b       -> g_expout
    mma_gemm2<HH, DD, false><<<dim3(DD / BN, BB / BM, N_EXP), 256, SMEM_BYTES>>>(
        g_hidden_p, nullptr, shr_w2, spec_w2, shr_b2, spec_b2, g_expout_p, 0);

    combine<<<dim3(DD / 256, BB), 256>>>(out);
}

// round 4
// speedup vs baseline: 3.1618x; 1.3807x over previous
#include <cuda_runtime.h>
#include <cuda_fp16.h>
#include <cstdint>
#include <cstddef>

// ---------------- problem constants ----------------
constexpr int T_TASKS = 4;
constexpr int NE_SH   = 4;
constexpr int DD      = 1024;
constexpr int HH      = 2048;
constexpr int BB      = 4096;
constexpr int N_EXP   = 20;

// ---------------- scratch ----------------
__device__ __half g_task_h[(size_t)T_TASKS * BB * DD];   // fp16 task_reps
__device__ __half g_shr_h [(size_t)BB * DD];             // fp16 shared_rep
__device__ __half g_hid_h [(size_t)N_EXP * BB * HH];     // fp16 hidden (L1 out)
__device__ float  g_expout[(size_t)N_EXP * BB * DD];     // fp32 expert outputs
__device__ __half g_w1h[(size_t)N_EXP * HH * DD];        // W1^T hi [N=H][K=D]
__device__ __half g_w1l[(size_t)N_EXP * HH * DD];        // W1^T lo
__device__ __half g_w2h[(size_t)N_EXP * DD * HH];        // W2^T hi [N=D][K=H]
__device__ __half g_w2l[(size_t)N_EXP * DD * HH];        // W2^T lo
__device__ float  g_gw [(size_t)T_TASKS * BB * 8];
__device__ float  g_sgw[(size_t)BB * 20];

// ---------------- PTX helpers ----------------
__device__ __forceinline__ uint32_t smem_u32(const void* p) {
    uint32_t a;
    asm("{ .reg .u64 t; cvta.to.shared.u64 t, %1; cvt.u32.u64 %0, t; }" : "=r"(a) : "l"(p));
    return a;
}
__device__ __forceinline__ void cp16(uint32_t dst, const void* src) {
    asm volatile("cp.async.cg.shared.global [%0], [%1], 16;" :: "r"(dst), "l"(src) : "memory");
}
#define CP_COMMIT() asm volatile("cp.async.commit_group;" ::: "memory")
#define CP_WAIT(n)  asm volatile("cp.async.wait_group %0;" :: "n"(n) : "memory")

__device__ __forceinline__ void mma_fp16(float* d, const uint32_t* a, uint32_t b0, uint32_t b1) {
    asm volatile(
        "mma.sync.aligned.m16n8k16.row.col.f32.f16.f16.f32 "
        "{%0,%1,%2,%3}, {%4,%5,%6,%7}, {%8,%9}, {%0,%1,%2,%3};"
        : "+f"(d[0]), "+f"(d[1]), "+f"(d[2]), "+f"(d[3])
        : "r"(a[0]), "r"(a[1]), "r"(a[2]), "r"(a[3]), "r"(b0), "r"(b1));
}

// ---------------- GEMM config ----------------
constexpr int BM = 256, BN = 128, BK = 32, STAGES = 4;
constexpr int ROWW  = 20;                   // u32 words per smem row (16 data + 4 pad)
constexpr int A_W   = BM * ROWW;            // 5120 words
constexpr int B_W   = BN * ROWW;            // 2560 words
constexpr int STG_W = A_W + 2 * B_W;        // 10240 words / stage
constexpr size_t SMEM_BYTES = (size_t)STAGES * STG_W * 4;   // 163840 B

// ---------------- fp16x2 tensor-core GEMM ----------------
// Out[m,n] = Ah[m,:] . (WTh[n,:] + WTl[n,:]) + bias[n]
template <int K, int NOUT, bool RELU, bool OUT_HALF>
__global__ void __launch_bounds__(256, 1)
gemm_fp16x2(const __half* __restrict__ Abase0, const __half* __restrict__ Abase1,
            const __half* __restrict__ Wh, const __half* __restrict__ Wl,
            const float* __restrict__ b_shr, const float* __restrict__ b_spec,
            void* __restrict__ OutBase, int a_split)
{
    extern __shared__ __align__(16) uint32_t sm32[];
    const int tid = threadIdx.x, lane = tid & 31, wid = tid >> 5;
    const int wm = wid & 3, wn = wid >> 2;          // 4 x 2 warp grid, warp tile 64x64
    const int gID = lane >> 2, tg = lane & 3;
    const int z  = blockIdx.z;
    const int m0 = blockIdx.y * BM, n0 = blockIdx.x * BN;

    const __half* A = a_split
        ? ((z < NE_SH) ? Abase0 : Abase1 + (size_t)((z - NE_SH) >> 2) * BB * K)
        : Abase0 + (size_t)z * BB * K;
    const __half* WTh = Wh + (size_t)z * (size_t)NOUT * K;
    const __half* WTl = Wl + (size_t)z * (size_t)NOUT * K;
    const float* bias = (z < NE_SH) ? b_shr + (size_t)z * NOUT
                                    : b_spec + (size_t)(z - NE_SH) * NOUT;

    const uint32_t smb = smem_u32(sm32);

    // per-thread producer bases: row = tid>>2 (+64*i), chunk = tid&3 (16B)
    const int pr = tid >> 2, pc = tid & 3;
    const __half* aSrc  = A   + (size_t)(m0 + pr) * K + pc * 8;
    const __half* bhSrc = WTh + (size_t)(n0 + pr) * K + pc * 8;
    const __half* blSrc = WTl + (size_t)(n0 + pr) * K + pc * 8;
    const uint32_t pDst = smb + pr * 80 + pc * 16;

#define ISSUE_STAGE(s, slot)                                                      \
    {                                                                             \
        const uint32_t so = (uint32_t)(slot) * (STG_W * 4);                       \
        const size_t   ko = (size_t)(s) * BK;                                     \
        _Pragma("unroll")                                                         \
        for (int i = 0; i < 4; i++)                                               \
            cp16(pDst + so + i * (64 * 80), aSrc + (size_t)i * 64 * K + ko);      \
        _Pragma("unroll")                                                         \
        for (int i = 0; i < 2; i++) {                                             \
            cp16(pDst + so + A_W * 4 + i * (64 * 80),                             \
                 bhSrc + (size_t)i * 64 * K + ko);                                \
            cp16(pDst + so + (A_W + B_W) * 4 + i * (64 * 80),                     \
                 blSrc + (size_t)i * 64 * K + ko);                                \
        }                                                                         \
    }

    float acc[4][8][4];
#pragma unroll
    for (int mt = 0; mt < 4; mt++)
#pragma unroll
        for (int nt = 0; nt < 8; nt++)
#pragma unroll
            for (int r = 0; r < 4; r++) acc[mt][nt][r] = 0.f;

    constexpr int NS = K / BK;

    // prologue: stages 0..STAGES-2
#pragma unroll
    for (int s = 0; s < STAGES - 1; s++) { ISSUE_STAGE(s, s); CP_COMMIT(); }

    for (int s = 0; s < NS; s++) {
        CP_WAIT(STAGES - 2);
        __syncthreads();

        const int ns = s + STAGES - 1;
        if (ns < NS) ISSUE_STAGE(ns, ns & (STAGES - 1));
        CP_COMMIT();

        const uint32_t* sa  = sm32 + (s & (STAGES - 1)) * STG_W;
        const uint32_t* sbh = sa + A_W;
        const uint32_t* sbl = sbh + B_W;

#pragma unroll
        for (int g = 0; g < 2; g++) {
            uint32_t a[4][4];
#pragma unroll
            for (int mt = 0; mt < 4; mt++) {
                const int r  = wm * 64 + mt * 16 + gID;
                const int w0 = r * ROWW + tg + 8 * g;
                a[mt][0] = sa[w0];
                a[mt][1] = sa[w0 + 8 * ROWW];
                a[mt][2] = sa[w0 + 4];
                a[mt][3] = sa[w0 + 8 * ROWW + 4];
            }
#pragma unroll
            for (int nt = 0; nt < 8; nt++) {
                const int n = wn * 64 + nt * 8 + gID;
                const int w = n * ROWW + tg + 8 * g;
                const uint32_t bh0 = sbh[w], bh1 = sbh[w + 4];
                const uint32_t bl0 = sbl[w], bl1 = sbl[w + 4];
#pragma unroll
                for (int mt = 0; mt < 4; mt++) {
                    mma_fp16(acc[mt][nt], a[mt], bh0, bh1);
                    mma_fp16(acc[mt][nt], a[mt], bl0, bl1);
                }
            }
        }
    }
#undef ISSUE_STAGE
    CP_WAIT(0);

    // --------- epilogue ---------
#pragma unroll
    for (int nt = 0; nt < 8; nt++) {
        const int col = n0 + wn * 64 + nt * 8 + 2 * tg;
        const float2 bv = *(const float2*)(bias + col);
#pragma unroll
        for (int mt = 0; mt < 4; mt++) {
            const int row = m0 + wm * 64 + mt * 16 + gID;
            float v0 = acc[mt][nt][0] + bv.x;
            float v1 = acc[mt][nt][1] + bv.y;
            float v2 = acc[mt][nt][2] + bv.x;
            float v3 = acc[mt][nt][3] + bv.y;
            if (RELU) {
                v0 = fmaxf(v0, 0.f); v1 = fmaxf(v1, 0.f);
                v2 = fmaxf(v2, 0.f); v3 = fmaxf(v3, 0.f);
            }
            if (OUT_HALF) {
                __half* Out = (__half*)OutBase + (size_t)z * BB * NOUT;
                *(__half2*)(Out + (size_t)row * NOUT + col)       = __floats2half2_rn(v0, v1);
                *(__half2*)(Out + (size_t)(row + 8) * NOUT + col) = __floats2half2_rn(v2, v3);
            } else {
                float* Out = (float*)OutBase + (size_t)z * BB * NOUT;
                *(float2*)(Out + (size_t)row * NOUT + col)       = make_float2(v0, v1);
                *(float2*)(Out + (size_t)(row + 8) * NOUT + col) = make_float2(v2, v3);
            }
        }
    }
}

// ---------------- weight split + transpose: W [K,N] fp32 -> WT hi/lo [N,K] fp16 ----------------
template <int K, int N>
__global__ void __launch_bounds__(256)
split_w(const float* __restrict__ shr, const float* __restrict__ spec,
        __half* __restrict__ outh, __half* __restrict__ outl)
{
    __shared__ float t[32][33];
    const int z = blockIdx.z;
    const float* src = (z < NE_SH) ? shr + (size_t)z * K * N
                                   : spec + (size_t)(z - NE_SH) * K * N;
    const int x0 = blockIdx.x * 32;   // N dir
    const int y0 = blockIdx.y * 32;   // K dir
    const int tx = threadIdx.x & 31, ty = threadIdx.x >> 5;
#pragma unroll
    for (int i = 0; i < 32; i += 8)
        t[ty + i][tx] = src[(size_t)(y0 + ty + i) * N + x0 + tx];
    __syncthreads();
    __half* oh = outh + (size_t)z * (size_t)N * K;
    __half* ol = outl + (size_t)z * (size_t)N * K;
#pragma unroll
    for (int i = 0; i < 32; i += 8) {
        const float w = t[tx][ty + i];
        const __half h = __float2half_rn(w);
        const __half l = __float2half_rn(w - __half2float(h));
        const size_t idx = (size_t)(x0 + ty + i) * K + y0 + tx;
        oh[idx] = h;
        ol[idx] = l;
    }
}

// ---------------- activation fp32 -> fp16 ----------------
__global__ void __launch_bounds__(256)
f2h(const float* __restrict__ src, __half* __restrict__ dst, int n4)
{
    const int i = blockIdx.x * 256 + threadIdx.x;
    if (i < n4) {
        const float4 v = ((const float4*)src)[i];
        ((__half2*)dst)[2 * i]     = __floats2half2_rn(v.x, v.y);
        ((__half2*)dst)[2 * i + 1] = __floats2half2_rn(v.z, v.w);
    }
}

// ---------------- gates (validated R0) ----------------
__global__ __launch_bounds__(256)
void gates_task(const float* __restrict__ task_reps,
                const float* __restrict__ gate_w, const float* __restrict__ gate_b)
{
    const int warp = blockIdx.x * 8 + (threadIdx.x >> 5);
    const int lane = threadIdx.x & 31;
    const int t = warp / BB;
    const float* x = task_reps + (size_t)warp * DD;
    const float* W = gate_w + (size_t)t * DD * 8;

    const int e = lane & 7, part = lane >> 3;
    float s = 0.f;
#pragma unroll 4
    for (int i = 0; i < DD / 4; i++) {
        const int d = part + 4 * i;
        s += x[d] * W[32 * i + lane];
    }
    s += __shfl_xor_sync(0xffffffffu, s, 8);
    s += __shfl_xor_sync(0xffffffffu, s, 16);
    s += gate_b[t * 8 + e];

    float m = s;
    m = fmaxf(m, __shfl_xor_sync(0xffffffffu, m, 1));
    m = fmaxf(m, __shfl_xor_sync(0xffffffffu, m, 2));
    m = fmaxf(m, __shfl_xor_sync(0xffffffffu, m, 4));
    float ex = expf(s - m);
    float sum = ex;
    sum += __shfl_xor_sync(0xffffffffu, sum, 1);
    sum += __shfl_xor_sync(0xffffffffu, sum, 2);
    sum += __shfl_xor_sync(0xffffffffu, sum, 4);
    if (lane < 8) g_gw[(size_t)warp * 8 + lane] = ex / sum;
}

__global__ __launch_bounds__(256)
void gates_shared(const float* __restrict__ shared_rep,
                  const float* __restrict__ sgate_w, const float* __restrict__ sgate_b)
{
    const int b = blockIdx.x * 8 + (threadIdx.x >> 5);
    const int lane = threadIdx.x & 31;
    const float* x = shared_rep + (size_t)b * DD;

    float s = 0.f;
    if (lane < 20) {
#pragma unroll 4
        for (int d = 0; d < DD; d++) s += x[d] * sgate_w[d * 20 + lane];
        s += sgate_b[lane];
    }
    float v = (lane < 20) ? s : -3.402823466e38f;
    float m = v;
    m = fmaxf(m, __shfl_xor_sync(0xffffffffu, m, 16));
    m = fmaxf(m, __shfl_xor_sync(0xffffffffu, m, 8));
    m = fmaxf(m, __shfl_xor_sync(0xffffffffu, m, 4));
    m = fmaxf(m, __shfl_xor_sync(0xffffffffu, m, 2));
    m = fmaxf(m, __shfl_xor_sync(0xffffffffu, m, 1));
    float ex = (lane < 20) ? expf(s - m) : 0.f;
    float sum = ex;
    sum += __shfl_xor_sync(0xffffffffu, sum, 16);
    sum += __shfl_xor_sync(0xffffffffu, sum, 8);
    sum += __shfl_xor_sync(0xffffffffu, sum, 4);
    sum += __shfl_xor_sync(0xffffffffu, sum, 2);
    sum += __shfl_xor_sync(0xffffffffu, sum, 1);
    if (lane < 20) g_sgw[(size_t)b * 20 + lane] = ex / sum;
}

// ---------------- combine (validated R0) ----------------
__global__ __launch_bounds__(256)
void combine(float* __restrict__ out)
{
    __shared__ float gw_s[T_TASKS][8];
    __shared__ float sgw_s[20];
    const int b = blockIdx.y;
    const int d = blockIdx.x * 256 + threadIdx.x;
    const int tid = threadIdx.x;

    if (tid < 32) {
        gw_s[tid >> 3][tid & 7] = g_gw[((size_t)(tid >> 3) * BB + b) * 8 + (tid & 7)];
    } else if (tid < 52) {
        sgw_s[tid - 32] = g_sgw[(size_t)b * 20 + (tid - 32)];
    }
    __syncthreads();

    float at[T_TASKS] = {0.f, 0.f, 0.f, 0.f};
    float ash = 0.f;
#pragma unroll
    for (int z = 0; z < N_EXP; z++) {
        const float v = g_expout[((size_t)z * BB + b) * DD + d];
        ash += sgw_s[z] * v;
        if (z < NE_SH) {
#pragma unroll
            for (int t = 0; t < T_TASKS; t++) at[t] += gw_s[t][z] * v;
        } else {
            const int te = z - NE_SH;
            at[te >> 2] += gw_s[te >> 2][4 + (te & 3)] * v;
        }
    }
#pragma unroll
    for (int t = 0; t < T_TASKS; t++)
        out[((size_t)t * BB + b) * DD + d] = at[t];
    out[((size_t)T_TASKS * BB + b) * DD + d] = ash;
}

// ---------------- launch ----------------
extern "C" void kernel_launch(void* const* d_in, const int* in_sizes, int n_in,
                              void* d_out, int out_size)
{
    const float* task_reps  = (const float*)d_in[0];
    const float* shared_rep = (const float*)d_in[1];
    const float* spec_w1    = (const float*)d_in[2];
    const float* spec_b1    = (const float*)d_in[3];
    const float* spec_w2    = (const float*)d_in[4];
    const float* spec_b2    = (const float*)d_in[5];
    const float* shr_w1     = (const float*)d_in[6];
    const float* shr_b1     = (const float*)d_in[7];
    const float* shr_w2     = (const float*)d_in[8];
    const float* shr_b2     = (const float*)d_in[9];
    const float* gate_w     = (const float*)d_in[10];
    const float* gate_b     = (const float*)d_in[11];
    const float* sgate_w    = (const float*)d_in[12];
    const float* sgate_b    = (const float*)d_in[13];
    float* out = (float*)d_out;

    __half *task_h, *shr_h, *hid_h, *w1h, *w1l, *w2h, *w2l;
    float  *expout_p;
    cudaGetSymbolAddress((void**)&task_h,   g_task_h);
    cudaGetSymbolAddress((void**)&shr_h,    g_shr_h);
    cudaGetSymbolAddress((void**)&hid_h,    g_hid_h);
    cudaGetSymbolAddress((void**)&expout_p, g_expout);
    cudaGetSymbolAddress((void**)&w1h,      g_w1h);
    cudaGetSymbolAddress((void**)&w1l,      g_w1l);
    cudaGetSymbolAddress((void**)&w2h,      g_w2h);
    cudaGetSymbolAddress((void**)&w2l,      g_w2l);

    cudaFuncSetAttribute(gemm_fp16x2<DD, HH, true, true>,
                         cudaFuncAttributeMaxDynamicSharedMemorySize, (int)SMEM_BYTES);
    cudaFuncSetAttribute(gemm_fp16x2<HH, DD, false, false>,
                         cudaFuncAttributeMaxDynamicSharedMemorySize, (int)SMEM_BYTES);

    // pre-passes: weight split+transpose, activation fp16 convert, gates
    split_w<DD, HH><<<dim3(HH / 32, DD / 32, N_EXP), 256>>>(shr_w1, spec_w1, w1h, w1l);
    split_w<HH, DD><<<dim3(DD / 32, HH / 32, N_EXP), 256>>>(shr_w2, spec_w2, w2h, w2l);
    {
        const int n4t = T_TASKS * BB * DD / 4;
        f2h<<<(n4t + 255) / 256, 256>>>(task_reps, task_h, n4t);
        const int n4s = BB * DD / 4;
        f2h<<<(n4s + 255) / 256, 256>>>(shared_rep, shr_h, n4s);
    }
    gates_task<<<T_TASKS * BB / 8, 256>>>(task_reps, gate_w, gate_b);
    gates_shared<<<BB / 8, 256>>>(shared_rep, sgate_w, sgate_b);

    // L1: [B,1024] @ [1024,2048] + b, relu -> fp16 hidden
    gemm_fp16x2<DD, HH, true, true><<<dim3(HH / BN, BB / BM, N_EXP), 256, SMEM_BYTES>>>(
        shr_h, task_h, w1h, w1l, shr_b1, spec_b1, hid_h, 1);
    // L2: [B,2048] @ [2048,1024] + b -> fp32 expout
    gemm_fp16x2<HH, DD, false, false><<<dim3(DD / BN, BB / BM, N_EXP), 256, SMEM_BYTES>>>(
        hid_h, nullptr, w2h, w2l, shr_b2, spec_b2, expout_p, 0);

    combine<<<dim3(DD / 256, BB), 256>>>(out);
}

// round 5
// speedup vs baseline: 3.2777x; 1.0367x over previous
#include <cuda_runtime.h>
#include <cuda_fp16.h>
#include <cstdint>
#include <cstddef>

// ---------------- problem constants ----------------
constexpr int T_TASKS = 4;
constexpr int NE_SH   = 4;
constexpr int DD      = 1024;
constexpr int HH      = 2048;
constexpr int BB      = 4096;
constexpr int N_EXP   = 20;

// ---------------- scratch ----------------
__device__ __half g_task_h[(size_t)T_TASKS * BB * DD];
__device__ __half g_shr_h [(size_t)BB * DD];
__device__ __half g_hid_h [(size_t)N_EXP * BB * HH];
__device__ float  g_expout[(size_t)N_EXP * BB * DD];
__device__ __half g_w1h[(size_t)N_EXP * HH * DD];
__device__ __half g_w1l[(size_t)N_EXP * HH * DD];
__device__ __half g_w2h[(size_t)N_EXP * DD * HH];
__device__ __half g_w2l[(size_t)N_EXP * DD * HH];
__device__ float  g_gw [(size_t)T_TASKS * BB * 8];
__device__ float  g_sgw[(size_t)BB * 20];

// ---------------- PTX helpers ----------------
__device__ __forceinline__ uint32_t smem_u32(const void* p) {
    uint32_t a;
    asm("{ .reg .u64 t; cvta.to.shared.u64 t, %1; cvt.u32.u64 %0, t; }" : "=r"(a) : "l"(p));
    return a;
}
__device__ __forceinline__ void cp16(uint32_t dst, const void* src) {
    asm volatile("cp.async.cg.shared.global [%0], [%1], 16;" :: "r"(dst), "l"(src) : "memory");
}
#define CP_COMMIT() asm volatile("cp.async.commit_group;" ::: "memory")
#define CP_WAIT(n)  asm volatile("cp.async.wait_group %0;" :: "n"(n) : "memory")

__device__ __forceinline__ void mma_fp16(float* d, const uint32_t* a, uint32_t b0, uint32_t b1) {
    asm volatile(
        "mma.sync.aligned.m16n8k16.row.col.f32.f16.f16.f32 "
        "{%0,%1,%2,%3}, {%4,%5,%6,%7}, {%8,%9}, {%0,%1,%2,%3};"
        : "+f"(d[0]), "+f"(d[1]), "+f"(d[2]), "+f"(d[3])
        : "r"(a[0]), "r"(a[1]), "r"(a[2]), "r"(a[3]), "r"(b0), "r"(b1));
}
__device__ __forceinline__ void ldsm4(uint32_t* r, uint32_t addr) {
    asm volatile("ldmatrix.sync.aligned.m8n8.x4.shared.b16 {%0,%1,%2,%3}, [%4];"
        : "=r"(r[0]), "=r"(r[1]), "=r"(r[2]), "=r"(r[3]) : "r"(addr));
}

// ---------------- GEMM config ----------------
constexpr int BM = 256, BN = 128, BK = 32, STAGES = 4;
constexpr int ROWW  = 20;                   // u32 words per smem row (16 data + 4 pad)
constexpr int A_W   = BM * ROWW;            // 5120 words
constexpr int B_W   = BN * ROWW;            // 2560 words
constexpr int STG_W = A_W + 2 * B_W;        // 10240 words / stage
constexpr size_t SMEM_BYTES = (size_t)STAGES * STG_W * 4;   // 163840 B

// ---------------- fp16x2 tensor-core GEMM (ldmatrix consumer) ----------------
// Out[m,n] = Ah[m,:] . (WTh[n,:] + WTl[n,:]) + bias[n]
template <int K, int NOUT, bool RELU, bool OUT_HALF>
__global__ void __launch_bounds__(256, 1)
gemm_fp16x2(const __half* __restrict__ Abase0, const __half* __restrict__ Abase1,
            const __half* __restrict__ Wh, const __half* __restrict__ Wl,
            const float* __restrict__ b_shr, const float* __restrict__ b_spec,
            void* __restrict__ OutBase, int a_split)
{
    extern __shared__ __align__(16) uint32_t sm32[];
    const int tid = threadIdx.x, lane = tid & 31, wid = tid >> 5;
    const int wm = wid & 3, wn = wid >> 2;          // 4 x 2 warp grid, warp tile 64x64
    const int gID = lane >> 2, tg = lane & 3;
    const int z  = blockIdx.z;
    const int m0 = blockIdx.y * BM, n0 = blockIdx.x * BN;

    const __half* A = a_split
        ? ((z < NE_SH) ? Abase0 : Abase1 + (size_t)((z - NE_SH) >> 2) * BB * K)
        : Abase0 + (size_t)z * BB * K;
    const __half* WTh = Wh + (size_t)z * (size_t)NOUT * K;
    const __half* WTl = Wl + (size_t)z * (size_t)NOUT * K;
    const float* bias = (z < NE_SH) ? b_shr + (size_t)z * NOUT
                                    : b_spec + (size_t)(z - NE_SH) * NOUT;

    const uint32_t smb = smem_u32(sm32);

    // producer bases: row = tid>>2 (+64*i), 16B chunk = tid&3
    const int pr = tid >> 2, pc = tid & 3;
    const __half* aSrc  = A   + (size_t)(m0 + pr) * K + pc * 8;
    const __half* bhSrc = WTh + (size_t)(n0 + pr) * K + pc * 8;
    const __half* blSrc = WTl + (size_t)(n0 + pr) * K + pc * 8;
    const uint32_t pDst = smb + pr * 80 + pc * 16;

    // consumer (ldmatrix) per-lane base addresses
    const uint32_t aBase  = smb + (uint32_t)(wm * 64 + (lane & 15)) * 80
                                + (uint32_t)((lane >> 4) * 16);
    const uint32_t bhBase = smb + A_W * 4
                                + (uint32_t)(wn * 64 + (lane & 7) + (lane >> 4) * 8) * 80
                                + (uint32_t)(((lane >> 3) & 1) * 16);
    const uint32_t blBase = bhBase + B_W * 4;

#define ISSUE_STAGE(s, slot)                                                      \
    {                                                                             \
        const uint32_t so = (uint32_t)(slot) * (STG_W * 4);                       \
        const size_t   ko = (size_t)(s) * BK;                                     \
        _Pragma("unroll")                                                         \
        for (int i = 0; i < 4; i++)                                               \
            cp16(pDst + so + i * (64 * 80), aSrc + (size_t)i * 64 * K + ko);      \
        _Pragma("unroll")                                                         \
        for (int i = 0; i < 2; i++) {                                             \
            cp16(pDst + so + A_W * 4 + i * (64 * 80),                             \
                 bhSrc + (size_t)i * 64 * K + ko);                                \
            cp16(pDst + so + (A_W + B_W) * 4 + i * (64 * 80),                     \
                 blSrc + (size_t)i * 64 * K + ko);                                \
        }                                                                         \
    }

    float acc[4][8][4];
#pragma unroll
    for (int mt = 0; mt < 4; mt++)
#pragma unroll
        for (int nt = 0; nt < 8; nt++)
#pragma unroll
            for (int r = 0; r < 4; r++) acc[mt][nt][r] = 0.f;

    constexpr int NS = K / BK;

#pragma unroll
    for (int s = 0; s < STAGES - 1; s++) { ISSUE_STAGE(s, s); CP_COMMIT(); }

    for (int s = 0; s < NS; s++) {
        CP_WAIT(STAGES - 2);
        __syncthreads();

        const int ns = s + STAGES - 1;
        if (ns < NS) ISSUE_STAGE(ns, ns & (STAGES - 1));
        CP_COMMIT();

        const uint32_t so = (uint32_t)(s & (STAGES - 1)) * (STG_W * 4);

#pragma unroll
        for (int g = 0; g < 2; g++) {
            uint32_t a[4][4], bh[4][4], bl[4][4];
#pragma unroll
            for (int mt = 0; mt < 4; mt++)
                ldsm4(a[mt], aBase + so + mt * (16 * 80) + g * 32);
#pragma unroll
            for (int p = 0; p < 4; p++)
                ldsm4(bh[p], bhBase + so + p * (16 * 80) + g * 32);
#pragma unroll
            for (int p = 0; p < 4; p++)
                ldsm4(bl[p], blBase + so + p * (16 * 80) + g * 32);

#pragma unroll
            for (int nt = 0; nt < 8; nt++) {
                const int p = nt >> 1, h = (nt & 1) * 2;
                const uint32_t bh0 = bh[p][h], bh1 = bh[p][h + 1];
                const uint32_t bl0 = bl[p][h], bl1 = bl[p][h + 1];
#pragma unroll
                for (int mt = 0; mt < 4; mt++) {
                    mma_fp16(acc[mt][nt], a[mt], bh0, bh1);
                    mma_fp16(acc[mt][nt], a[mt], bl0, bl1);
                }
            }
        }
    }
#undef ISSUE_STAGE
    CP_WAIT(0);

    // --------- epilogue ---------
#pragma unroll
    for (int nt = 0; nt < 8; nt++) {
        const int col = n0 + wn * 64 + nt * 8 + 2 * tg;
        const float2 bv = *(const float2*)(bias + col);
#pragma unroll
        for (int mt = 0; mt < 4; mt++) {
            const int row = m0 + wm * 64 + mt * 16 + gID;
            float v0 = acc[mt][nt][0] + bv.x;
            float v1 = acc[mt][nt][1] + bv.y;
            float v2 = acc[mt][nt][2] + bv.x;
            float v3 = acc[mt][nt][3] + bv.y;
            if (RELU) {
                v0 = fmaxf(v0, 0.f); v1 = fmaxf(v1, 0.f);
                v2 = fmaxf(v2, 0.f); v3 = fmaxf(v3, 0.f);
            }
            if (OUT_HALF) {
                __half* Out = (__half*)OutBase + (size_t)z * BB * NOUT;
                *(__half2*)(Out + (size_t)row * NOUT + col)       = __floats2half2_rn(v0, v1);
                *(__half2*)(Out + (size_t)(row + 8) * NOUT + col) = __floats2half2_rn(v2, v3);
            } else {
                float* Out = (float*)OutBase + (size_t)z * BB * NOUT;
                *(float2*)(Out + (size_t)row * NOUT + col)       = make_float2(v0, v1);
                *(float2*)(Out + (size_t)(row + 8) * NOUT + col) = make_float2(v2, v3);
            }
        }
    }
}

// ---------------- weight split + transpose ----------------
template <int K, int N>
__global__ void __launch_bounds__(256)
split_w(const float* __restrict__ shr, const float* __restrict__ spec,
        __half* __restrict__ outh, __half* __restrict__ outl)
{
    __shared__ float t[32][33];
    const int z = blockIdx.z;
    const float* src = (z < NE_SH) ? shr + (size_t)z * K * N
                                   : spec + (size_t)(z - NE_SH) * K * N;
    const int x0 = blockIdx.x * 32;
    const int y0 = blockIdx.y * 32;
    const int tx = threadIdx.x & 31, ty = threadIdx.x >> 5;
#pragma unroll
    for (int i = 0; i < 32; i += 8)
        t[ty + i][tx] = src[(size_t)(y0 + ty + i) * N + x0 + tx];
    __syncthreads();
    __half* oh = outh + (size_t)z * (size_t)N * K;
    __half* ol = outl + (size_t)z * (size_t)N * K;
#pragma unroll
    for (int i = 0; i < 32; i += 8) {
        const float w = t[tx][ty + i];
        const __half h = __float2half_rn(w);
        const __half l = __float2half_rn(w - __half2float(h));
        const size_t idx = (size_t)(x0 + ty + i) * K + y0 + tx;
        oh[idx] = h;
        ol[idx] = l;
    }
}

// ---------------- activation fp32 -> fp16 ----------------
__global__ void __launch_bounds__(256)
f2h(const float* __restrict__ src, __half* __restrict__ dst, int n4)
{
    const int i = blockIdx.x * 256 + threadIdx.x;
    if (i < n4) {
        const float4 v = ((const float4*)src)[i];
        ((__half2*)dst)[2 * i]     = __floats2half2_rn(v.x, v.y);
        ((__half2*)dst)[2 * i + 1] = __floats2half2_rn(v.z, v.w);
    }
}

// ---------------- gates ----------------
__global__ __launch_bounds__(256)
void gates_task(const float* __restrict__ task_reps,
                const float* __restrict__ gate_w, const float* __restrict__ gate_b)
{
    const int warp = blockIdx.x * 8 + (threadIdx.x >> 5);
    const int lane = threadIdx.x & 31;
    const int t = warp / BB;
    const float* x = task_reps + (size_t)warp * DD;
    const float* W = gate_w + (size_t)t * DD * 8;

    const int e = lane & 7, part = lane >> 3;
    float s = 0.f;
#pragma unroll 4
    for (int i = 0; i < DD / 4; i++) {
        const int d = part + 4 * i;
        s += x[d] * W[32 * i + lane];
    }
    s += __shfl_xor_sync(0xffffffffu, s, 8);
    s += __shfl_xor_sync(0xffffffffu, s, 16);
    s += gate_b[t * 8 + e];

    float m = s;
    m = fmaxf(m, __shfl_xor_sync(0xffffffffu, m, 1));
    m = fmaxf(m, __shfl_xor_sync(0xffffffffu, m, 2));
    m = fmaxf(m, __shfl_xor_sync(0xffffffffu, m, 4));
    float ex = expf(s - m);
    float sum = ex;
    sum += __shfl_xor_sync(0xffffffffu, sum, 1);
    sum += __shfl_xor_sync(0xffffffffu, sum, 2);
    sum += __shfl_xor_sync(0xffffffffu, sum, 4);
    if (lane < 8) g_gw[(size_t)warp * 8 + lane] = ex / sum;
}

__global__ __launch_bounds__(256)
void gates_shared(const float* __restrict__ shared_rep,
                  const float* __restrict__ sgate_w, const float* __restrict__ sgate_b)
{
    const int b = blockIdx.x * 8 + (threadIdx.x >> 5);
    const int lane = threadIdx.x & 31;
    const float* x = shared_rep + (size_t)b * DD;

    float s = 0.f;
    if (lane < 20) {
#pragma unroll 4
        for (int d = 0; d < DD; d++) s += x[d] * sgate_w[d * 20 + lane];
        s += sgate_b[lane];
    }
    float v = (lane < 20) ? s : -3.402823466e38f;
    float m = v;
    m = fmaxf(m, __shfl_xor_sync(0xffffffffu, m, 16));
    m = fmaxf(m, __shfl_xor_sync(0xffffffffu, m, 8));
    m = fmaxf(m, __shfl_xor_sync(0xffffffffu, m, 4));
    m = fmaxf(m, __shfl_xor_sync(0xffffffffu, m, 2));
    m = fmaxf(m, __shfl_xor_sync(0xffffffffu, m, 1));
    float ex = (lane < 20) ? expf(s - m) : 0.f;
    float sum = ex;
    sum += __shfl_xor_sync(0xffffffffu, sum, 16);
    sum += __shfl_xor_sync(0xffffffffu, sum, 8);
    sum += __shfl_xor_sync(0xffffffffu, sum, 4);
    sum += __shfl_xor_sync(0xffffffffu, sum, 2);
    sum += __shfl_xor_sync(0xffffffffu, sum, 1);
    if (lane < 20) g_sgw[(size_t)b * 20 + lane] = ex / sum;
}

// ---------------- combine ----------------
__global__ __launch_bounds__(256)
void combine(float* __restrict__ out)
{
    __shared__ float gw_s[T_TASKS][8];
    __shared__ float sgw_s[20];
    const int b = blockIdx.y;
    const int d = blockIdx.x * 256 + threadIdx.x;
    const int tid = threadIdx.x;

    if (tid < 32) {
        gw_s[tid >> 3][tid & 7] = g_gw[((size_t)(tid >> 3) * BB + b) * 8 + (tid & 7)];
    } else if (tid < 52) {
        sgw_s[tid - 32] = g_sgw[(size_t)b * 20 + (tid - 32)];
    }
    __syncthreads();

    float at[T_TASKS] = {0.f, 0.f, 0.f, 0.f};
    float ash = 0.f;
#pragma unroll
    for (int z = 0; z < N_EXP; z++) {
        const float v = g_expout[((size_t)z * BB + b) * DD + d];
        ash += sgw_s[z] * v;
        if (z < NE_SH) {
#pragma unroll
            for (int t = 0; t < T_TASKS; t++) at[t] += gw_s[t][z] * v;
        } else {
            const int te = z - NE_SH;
            at[te >> 2] += gw_s[te >> 2][4 + (te & 3)] * v;
        }
    }
#pragma unroll
    for (int t = 0; t < T_TASKS; t++)
        out[((size_t)t * BB + b) * DD + d] = at[t];
    out[((size_t)T_TASKS * BB + b) * DD + d] = ash;
}

// ---------------- launch ----------------
extern "C" void kernel_launch(void* const* d_in, const int* in_sizes, int n_in,
                              void* d_out, int out_size)
{
    const float* task_reps  = (const float*)d_in[0];
    const float* shared_rep = (const float*)d_in[1];
    const float* spec_w1    = (const float*)d_in[2];
    const float* spec_b1    = (const float*)d_in[3];
    const float* spec_w2    = (const float*)d_in[4];
    const float* spec_b2    = (const float*)d_in[5];
    const float* shr_w1     = (const float*)d_in[6];
    const float* shr_b1     = (const float*)d_in[7];
    const float* shr_w2     = (const float*)d_in[8];
    const float* shr_b2     = (const float*)d_in[9];
    const float* gate_w     = (const float*)d_in[10];
    const float* gate_b     = (const float*)d_in[11];
    const float* sgate_w    = (const float*)d_in[12];
    const float* sgate_b    = (const float*)d_in[13];
    float* out = (float*)d_out;

    __half *task_h, *shr_h, *hid_h, *w1h, *w1l, *w2h, *w2l;
    float  *expout_p;
    cudaGetSymbolAddress((void**)&task_h,   g_task_h);
    cudaGetSymbolAddress((void**)&shr_h,    g_shr_h);
    cudaGetSymbolAddress((void**)&hid_h,    g_hid_h);
    cudaGetSymbolAddress((void**)&expout_p, g_expout);
    cudaGetSymbolAddress((void**)&w1h,      g_w1h);
    cudaGetSymbolAddress((void**)&w1l,      g_w1l);
    cudaGetSymbolAddress((void**)&w2h,      g_w2h);
    cudaGetSymbolAddress((void**)&w2l,      g_w2l);

    cudaFuncSetAttribute(gemm_fp16x2<DD, HH, true, true>,
                         cudaFuncAttributeMaxDynamicSharedMemorySize, (int)SMEM_BYTES);
    cudaFuncSetAttribute(gemm_fp16x2<HH, DD, false, false>,
                         cudaFuncAttributeMaxDynamicSharedMemorySize, (int)SMEM_BYTES);

    split_w<DD, HH><<<dim3(HH / 32, DD / 32, N_EXP), 256>>>(shr_w1, spec_w1, w1h, w1l);
    split_w<HH, DD><<<dim3(DD / 32, HH / 32, N_EXP), 256>>>(shr_w2, spec_w2, w2h, w2l);
    {
        const int n4t = T_TASKS * BB * DD / 4;
        f2h<<<(n4t + 255) / 256, 256>>>(task_reps, task_h, n4t);
        const int n4s = BB * DD / 4;
        f2h<<<(n4s + 255) / 256, 256>>>(shared_rep, shr_h, n4s);
    }
    gates_task<<<T_TASKS * BB / 8, 256>>>(task_reps, gate_w, gate_b);
    gates_shared<<<BB / 8, 256>>>(shared_rep, sgate_w, sgate_b);

    gemm_fp16x2<DD, HH, true, true><<<dim3(HH / BN, BB / BM, N_EXP), 256, SMEM_BYTES>>>(
        shr_h, task_h, w1h, w1l, shr_b1, spec_b1, hid_h, 1);
    gemm_fp16x2<HH, DD, false, false><<<dim3(DD / BN, BB / BM, N_EXP), 256, SMEM_BYTES>>>(
        hid_h, nullptr, w2h, w2l, shr_b2, spec_b2, expout_p, 0);

    combine<<<dim3(DD / 256, BB), 256>>>(out);
}

// round 6
// speedup vs baseline: 5.9446x; 1.8136x over previous
#include <cuda_runtime.h>
#include <cuda_fp16.h>
#include <cstdint>
#include <cstddef>

// ---------------- problem constants ----------------
constexpr int T_TASKS = 4;
constexpr int NE_SH   = 4;
constexpr int DD      = 1024;
constexpr int HH      = 2048;
constexpr int BB      = 4096;
constexpr int N_EXP   = 20;

// ---------------- scratch ----------------
__device__ __half g_task_h[(size_t)T_TASKS * BB * DD];
__device__ __half g_shr_h [(size_t)BB * DD];
__device__ __half g_hid_h [(size_t)N_EXP * BB * HH];
__device__ float  g_expout[(size_t)N_EXP * BB * DD];
__device__ __half g_w1h[(size_t)N_EXP * HH * DD];     // W1^T fp16 [N=H][K=D]
__device__ __half g_w2h[(size_t)N_EXP * DD * HH];     // W2^T fp16 [N=D][K=H]
__device__ float  g_gw [(size_t)T_TASKS * BB * 8];
__device__ float  g_sgw[(size_t)BB * 20];

// ---------------- PTX helpers ----------------
__device__ __forceinline__ uint32_t smem_u32(const void* p) {
    uint32_t a;
    asm("{ .reg .u64 t; cvta.to.shared.u64 t, %1; cvt.u32.u64 %0, t; }" : "=r"(a) : "l"(p));
    return a;
}
__device__ __forceinline__ void cp16(uint32_t dst, const void* src) {
    asm volatile("cp.async.cg.shared.global [%0], [%1], 16;" :: "r"(dst), "l"(src) : "memory");
}
#define CP_COMMIT() asm volatile("cp.async.commit_group;" ::: "memory")
#define CP_WAIT(n)  asm volatile("cp.async.wait_group %0;" :: "n"(n) : "memory")

__device__ __forceinline__ void mma_fp16(float* d, const uint32_t* a, uint32_t b0, uint32_t b1) {
    asm volatile(
        "mma.sync.aligned.m16n8k16.row.col.f32.f16.f16.f32 "
        "{%0,%1,%2,%3}, {%4,%5,%6,%7}, {%8,%9}, {%0,%1,%2,%3};"
        : "+f"(d[0]), "+f"(d[1]), "+f"(d[2]), "+f"(d[3])
        : "r"(a[0]), "r"(a[1]), "r"(a[2]), "r"(a[3]), "r"(b0), "r"(b1));
}
__device__ __forceinline__ void ldsm4(uint32_t* r, uint32_t addr) {
    asm volatile("ldmatrix.sync.aligned.m8n8.x4.shared.b16 {%0,%1,%2,%3}, [%4];"
        : "=r"(r[0]), "=r"(r[1]), "=r"(r[2]), "=r"(r[3]) : "r"(addr));
}

// ---------------- GEMM config ----------------
constexpr int BM = 128, BN = 128, BK = 64, STAGES = 3;
constexpr int ROWB   = 144;                      // 128B data + 16B pad per row
constexpr int A_BY   = BM * ROWB;                // 18432 B
constexpr int B_BY   = BN * ROWB;                // 18432 B
constexpr int STG_BY = A_BY + B_BY;              // 36864 B
constexpr size_t SMEM_BYTES = (size_t)STAGES * STG_BY;   // 110592 B -> 2 CTAs/SM

// ---------------- pure-fp16 tensor-core GEMM, 2 CTAs/SM ----------------
// Out[m,n] = A16[m,:] . WT16[n,:] + bias[n]
template <int K, int NOUT, bool RELU, bool OUT_HALF>
__global__ void __launch_bounds__(256, 2)
gemm_fp16(const __half* __restrict__ Abase0, const __half* __restrict__ Abase1,
          const __half* __restrict__ Wh,
          const float* __restrict__ b_shr, const float* __restrict__ b_spec,
          void* __restrict__ OutBase, int a_split)
{
    extern __shared__ __align__(16) char smem[];
    const int tid = threadIdx.x, lane = tid & 31, wid = tid >> 5;
    const int wm = wid & 3, wn = wid >> 2;          // 4 x 2 warp grid, warp tile 32x64
    const int gID = lane >> 2, tg = lane & 3;
    const int z  = blockIdx.z;
    const int m0 = blockIdx.y * BM, n0 = blockIdx.x * BN;

    const __half* A = a_split
        ? ((z < NE_SH) ? Abase0 : Abase1 + (size_t)((z - NE_SH) >> 2) * BB * K)
        : Abase0 + (size_t)z * BB * K;
    const __half* WT = Wh + (size_t)z * (size_t)NOUT * K;
    const float* bias = (z < NE_SH) ? b_shr + (size_t)z * NOUT
                                    : b_spec + (size_t)(z - NE_SH) * NOUT;

    const uint32_t smb = smem_u32(smem);

    // producer: 128 rows x 8 chunks(16B) per tile; chunk = tid&7, rows tid>>3 + 32i
    const int prow = tid >> 3, pchk = tid & 7;
    const __half* aSrc = A  + (size_t)(m0 + prow) * K + pchk * 8;
    const __half* bSrc = WT + (size_t)(n0 + prow) * K + pchk * 8;
    const uint32_t pDst = smb + prow * ROWB + pchk * 16;

    // consumer (ldmatrix) per-lane bases
    const uint32_t aBase = smb + (uint32_t)(wm * 32 + (lane & 15)) * ROWB
                               + (uint32_t)((lane >> 4) * 16);
    const uint32_t bBase = smb + A_BY
                               + (uint32_t)(wn * 64 + (lane & 7) + (lane >> 4) * 8) * ROWB
                               + (uint32_t)(((lane >> 3) & 1) * 16);

#define ISSUE_STAGE(s, slot)                                                    \
    {                                                                           \
        const uint32_t so = (uint32_t)(slot) * STG_BY;                          \
        const size_t   ko = (size_t)(s) * BK;                                   \
        _Pragma("unroll")                                                       \
        for (int i = 0; i < 4; i++)                                             \
            cp16(pDst + so + i * (32 * ROWB), aSrc + (size_t)i * 32 * K + ko);  \
        _Pragma("unroll")                                                       \
        for (int i = 0; i < 4; i++)                                             \
            cp16(pDst + so + A_BY + i * (32 * ROWB),                            \
                 bSrc + (size_t)i * 32 * K + ko);                               \
    }

    float acc[2][8][4];
#pragma unroll
    for (int mt = 0; mt < 2; mt++)
#pragma unroll
        for (int nt = 0; nt < 8; nt++)
#pragma unroll
            for (int r = 0; r < 4; r++) acc[mt][nt][r] = 0.f;

    constexpr int NS = K / BK;

#pragma unroll
    for (int s = 0; s < STAGES - 1; s++) { ISSUE_STAGE(s, s); CP_COMMIT(); }

    int slot = 0;
    for (int s = 0; s < NS; s++) {
        CP_WAIT(STAGES - 2);
        __syncthreads();

        const int ns = s + STAGES - 1;
        int islot = slot + STAGES - 1; if (islot >= STAGES) islot -= STAGES;
        if (ns < NS) ISSUE_STAGE(ns, islot);
        CP_COMMIT();

        const uint32_t so = (uint32_t)slot * STG_BY;

#pragma unroll
        for (int g = 0; g < 4; g++) {
            uint32_t a[2][4], b[4][4];
#pragma unroll
            for (int mt = 0; mt < 2; mt++)
                ldsm4(a[mt], aBase + so + mt * (16 * ROWB) + g * 32);
#pragma unroll
            for (int p = 0; p < 4; p++)
                ldsm4(b[p], bBase + so + p * (16 * ROWB) + g * 32);

#pragma unroll
            for (int nt = 0; nt < 8; nt++) {
                const int p = nt >> 1, h = (nt & 1) * 2;
                const uint32_t b0 = b[p][h], b1 = b[p][h + 1];
#pragma unroll
                for (int mt = 0; mt < 2; mt++)
                    mma_fp16(acc[mt][nt], a[mt], b0, b1);
            }
        }
        if (++slot == STAGES) slot = 0;
    }
#undef ISSUE_STAGE
    CP_WAIT(0);

    // --------- epilogue ---------
#pragma unroll
    for (int nt = 0; nt < 8; nt++) {
        const int col = n0 + wn * 64 + nt * 8 + 2 * tg;
        const float2 bv = *(const float2*)(bias + col);
#pragma unroll
        for (int mt = 0; mt < 2; mt++) {
            const int row = m0 + wm * 32 + mt * 16 + gID;
            float v0 = acc[mt][nt][0] + bv.x;
            float v1 = acc[mt][nt][1] + bv.y;
            float v2 = acc[mt][nt][2] + bv.x;
            float v3 = acc[mt][nt][3] + bv.y;
            if (RELU) {
                v0 = fmaxf(v0, 0.f); v1 = fmaxf(v1, 0.f);
                v2 = fmaxf(v2, 0.f); v3 = fmaxf(v3, 0.f);
            }
            if (OUT_HALF) {
                __half* Out = (__half*)OutBase + (size_t)z * BB * NOUT;
                *(__half2*)(Out + (size_t)row * NOUT + col)       = __floats2half2_rn(v0, v1);
                *(__half2*)(Out + (size_t)(row + 8) * NOUT + col) = __floats2half2_rn(v2, v3);
            } else {
                float* Out = (float*)OutBase + (size_t)z * BB * NOUT;
                *(float2*)(Out + (size_t)row * NOUT + col)       = make_float2(v0, v1);
                *(float2*)(Out + (size_t)(row + 8) * NOUT + col) = make_float2(v2, v3);
            }
        }
    }
}

// ---------------- weight convert + transpose: W [K,N] fp32 -> WT [N,K] fp16 ----------------
template <int K, int N>
__global__ void __launch_bounds__(256)
conv_w(const float* __restrict__ shr, const float* __restrict__ spec,
       __half* __restrict__ outh)
{
    __shared__ float t[32][33];
    const int z = blockIdx.z;
    const float* src = (z < NE_SH) ? shr + (size_t)z * K * N
                                   : spec + (size_t)(z - NE_SH) * K * N;
    const int x0 = blockIdx.x * 32;   // N dir
    const int y0 = blockIdx.y * 32;   // K dir
    const int tx = threadIdx.x & 31, ty = threadIdx.x >> 5;
#pragma unroll
    for (int i = 0; i < 32; i += 8)
        t[ty + i][tx] = src[(size_t)(y0 + ty + i) * N + x0 + tx];
    __syncthreads();
    __half* oh = outh + (size_t)z * (size_t)N * K;
#pragma unroll
    for (int i = 0; i < 32; i += 8)
        oh[(size_t)(x0 + ty + i) * K + y0 + tx] = __float2half_rn(t[tx][ty + i]);
}

// ---------------- activation fp32 -> fp16 ----------------
__global__ void __launch_bounds__(256)
f2h(const float* __restrict__ src, __half* __restrict__ dst, int n4)
{
    const int i = blockIdx.x * 256 + threadIdx.x;
    if (i < n4) {
        const float4 v = ((const float4*)src)[i];
        ((__half2*)dst)[2 * i]     = __floats2half2_rn(v.x, v.y);
        ((__half2*)dst)[2 * i + 1] = __floats2half2_rn(v.z, v.w);
    }
}

// ---------------- gates ----------------
__global__ __launch_bounds__(256)
void gates_task(const float* __restrict__ task_reps,
                const float* __restrict__ gate_w, const float* __restrict__ gate_b)
{
    const int warp = blockIdx.x * 8 + (threadIdx.x >> 5);
    const int lane = threadIdx.x & 31;
    const int t = warp / BB;
    const float* x = task_reps + (size_t)warp * DD;
    const float* W = gate_w + (size_t)t * DD * 8;

    const int e = lane & 7, part = lane >> 3;
    float s = 0.f;
#pragma unroll 4
    for (int i = 0; i < DD / 4; i++) {
        const int d = part + 4 * i;
        s += x[d] * W[32 * i + lane];
    }
    s += __shfl_xor_sync(0xffffffffu, s, 8);
    s += __shfl_xor_sync(0xffffffffu, s, 16);
    s += gate_b[t * 8 + e];

    float m = s;
    m = fmaxf(m, __shfl_xor_sync(0xffffffffu, m, 1));
    m = fmaxf(m, __shfl_xor_sync(0xffffffffu, m, 2));
    m = fmaxf(m, __shfl_xor_sync(0xffffffffu, m, 4));
    float ex = expf(s - m);
    float sum = ex;
    sum += __shfl_xor_sync(0xffffffffu, sum, 1);
    sum += __shfl_xor_sync(0xffffffffu, sum, 2);
    sum += __shfl_xor_sync(0xffffffffu, sum, 4);
    if (lane < 8) g_gw[(size_t)warp * 8 + lane] = ex / sum;
}

__global__ __launch_bounds__(256)
void gates_shared(const float* __restrict__ shared_rep,
                  const float* __restrict__ sgate_w, const float* __restrict__ sgate_b)
{
    const int b = blockIdx.x * 8 + (threadIdx.x >> 5);
    const int lane = threadIdx.x & 31;
    const float* x = shared_rep + (size_t)b * DD;

    float s = 0.f;
    if (lane < 20) {
#pragma unroll 4
        for (int d = 0; d < DD; d++) s += x[d] * sgate_w[d * 20 + lane];
        s += sgate_b[lane];
    }
    float v = (lane < 20) ? s : -3.402823466e38f;
    float m = v;
    m = fmaxf(m, __shfl_xor_sync(0xffffffffu, m, 16));
    m = fmaxf(m, __shfl_xor_sync(0xffffffffu, m, 8));
    m = fmaxf(m, __shfl_xor_sync(0xffffffffu, m, 4));
    m = fmaxf(m, __shfl_xor_sync(0xffffffffu, m, 2));
    m = fmaxf(m, __shfl_xor_sync(0xffffffffu, m, 1));
    float ex = (lane < 20) ? expf(s - m) : 0.f;
    float sum = ex;
    sum += __shfl_xor_sync(0xffffffffu, sum, 16);
    sum += __shfl_xor_sync(0xffffffffu, sum, 8);
    sum += __shfl_xor_sync(0xffffffffu, sum, 4);
    sum += __shfl_xor_sync(0xffffffffu, sum, 2);
    sum += __shfl_xor_sync(0xffffffffu, sum, 1);
    if (lane < 20) g_sgw[(size_t)b * 20 + lane] = ex / sum;
}

// ---------------- combine ----------------
__global__ __launch_bounds__(256)
void combine(float* __restrict__ out)
{
    __shared__ float gw_s[T_TASKS][8];
    __shared__ float sgw_s[20];
    const int b = blockIdx.y;
    const int d = blockIdx.x * 256 + threadIdx.x;
    const int tid = threadIdx.x;

    if (tid < 32) {
        gw_s[tid >> 3][tid & 7] = g_gw[((size_t)(tid >> 3) * BB + b) * 8 + (tid & 7)];
    } else if (tid < 52) {
        sgw_s[tid - 32] = g_sgw[(size_t)b * 20 + (tid - 32)];
    }
    __syncthreads();

    float at[T_TASKS] = {0.f, 0.f, 0.f, 0.f};
    float ash = 0.f;
#pragma unroll
    for (int z = 0; z < N_EXP; z++) {
        const float v = g_expout[((size_t)z * BB + b) * DD + d];
        ash += sgw_s[z] * v;
        if (z < NE_SH) {
#pragma unroll
            for (int t = 0; t < T_TASKS; t++) at[t] += gw_s[t][z] * v;
        } else {
            const int te = z - NE_SH;
            at[te >> 2] += gw_s[te >> 2][4 + (te & 3)] * v;
        }
    }
#pragma unroll
    for (int t = 0; t < T_TASKS; t++)
        out[((size_t)t * BB + b) * DD + d] = at[t];
    out[((size_t)T_TASKS * BB + b) * DD + d] = ash;
}

// ---------------- launch ----------------
extern "C" void kernel_launch(void* const* d_in, const int* in_sizes, int n_in,
                              void* d_out, int out_size)
{
    const float* task_reps  = (const float*)d_in[0];
    const float* shared_rep = (const float*)d_in[1];
    const float* spec_w1    = (const float*)d_in[2];
    const float* spec_b1    = (const float*)d_in[3];
    const float* spec_w2    = (const float*)d_in[4];
    const float* spec_b2    = (const float*)d_in[5];
    const float* shr_w1     = (const float*)d_in[6];
    const float* shr_b1     = (const float*)d_in[7];
    const float* shr_w2     = (const float*)d_in[8];
    const float* shr_b2     = (const float*)d_in[9];
    const float* gate_w     = (const float*)d_in[10];
    const float* gate_b     = (const float*)d_in[11];
    const float* sgate_w    = (const float*)d_in[12];
    const float* sgate_b    = (const float*)d_in[13];
    float* out = (float*)d_out;

    __half *task_h, *shr_h, *hid_h, *w1h, *w2h;
    float  *expout_p;
    cudaGetSymbolAddress((void**)&task_h,   g_task_h);
    cudaGetSymbolAddress((void**)&shr_h,    g_shr_h);
    cudaGetSymbolAddress((void**)&hid_h,    g_hid_h);
    cudaGetSymbolAddress((void**)&expout_p, g_expout);
    cudaGetSymbolAddress((void**)&w1h,      g_w1h);
    cudaGetSymbolAddress((void**)&w2h,      g_w2h);

    cudaFuncSetAttribute(gemm_fp16<DD, HH, true, true>,
                         cudaFuncAttributeMaxDynamicSharedMemorySize, (int)SMEM_BYTES);
    cudaFuncSetAttribute(gemm_fp16<HH, DD, false, false>,
                         cudaFuncAttributeMaxDynamicSharedMemorySize, (int)SMEM_BYTES);

    conv_w<DD, HH><<<dim3(HH / 32, DD / 32, N_EXP), 256>>>(shr_w1, spec_w1, w1h);
    conv_w<HH, DD><<<dim3(DD / 32, HH / 32, N_EXP), 256>>>(shr_w2, spec_w2, w2h);
    {
        const int n4t = T_TASKS * BB * DD / 4;
        f2h<<<(n4t + 255) / 256, 256>>>(task_reps, task_h, n4t);
        const int n4s = BB * DD / 4;
        f2h<<<(n4s + 255) / 256, 256>>>(shared_rep, shr_h, n4s);
    }
    gates_task<<<T_TASKS * BB / 8, 256>>>(task_reps, gate_w, gate_b);
    gates_shared<<<BB / 8, 256>>>(shared_rep, sgate_w, sgate_b);

    // L1: [B,1024] @ [1024,2048] + b, relu -> fp16 hidden
    gemm_fp16<DD, HH, true, true><<<dim3(HH / BN, BB / BM, N_EXP), 256, SMEM_BYTES>>>(
        shr_h, task_h, w1h, shr_b1, spec_b1, hid_h, 1);
    // L2: [B,2048] @ [2048,1024] + b -> fp32 expout
    gemm_fp16<HH, DD, false, false><<<dim3(DD / BN, BB / BM, N_EXP), 256, SMEM_BYTES>>>(
        hid_h, nullptr, w2h, shr_b2, spec_b2, expout_p, 0);

    combine<<<dim3(DD / 256, BB), 256>>>(out);
}